// round 7
// baseline (speedup 1.0000x reference)
#include <cuda_runtime.h>
#include <math.h>

#define BB   4
#define NPTS 20000
#define CCH  256
#define NS   1024
#define NV   300

// output packing offsets (float32 elements, tuple order)
#define O_OBJ   0L        // (4,2,20000)  160000
#define O_GRASP 160000L   // (4,20000)     80000
#define O_GXYZ  240000L   // (4,1024,3)    12288
#define O_GIND  252288L   // (4,1024)       4096
#define O_GFEAT 256384L   // (4,256,1024) 1048576
#define O_FP2   1304960L  // (4,1024)       4096
#define O_VPXYZ 1309056L  // (4,1024,3)    12288
#define O_TOPV  1321344L  // (4,1024)       4096
#define O_VPROT 1325440L  // (4,1024,3,3)  36864
// total = 1362304

__device__ float g_h[BB * CCH * NPTS];     // hidden activations scratch
__device__ float g_f[BB * CCH * NS];       // second-stage activations
__device__ unsigned char g_mask[BB * NPTS];
__device__ int   g_inds[BB * NS];
__device__ float g_views[NV * 3];
__device__ float g_vnorm[NV];

// ---------------------------------------------------------------- packed f32x2 helpers
__device__ __forceinline__ unsigned long long pack2(float lo, float hi)
{
    unsigned long long r;
    asm("mov.b64 %0, {%1, %2};" : "=l"(r) : "f"(lo), "f"(hi));
    return r;
}
__device__ __forceinline__ void unpack2(unsigned long long v, float& lo, float& hi)
{
    asm("mov.b64 {%0, %1}, %2;" : "=f"(lo), "=f"(hi) : "l"(v));
}
__device__ __forceinline__ void ffma2(unsigned long long& d, unsigned long long a, unsigned long long b)
{
    asm("fma.rn.f32x2 %0, %1, %2, %0;" : "+l"(d) : "l"(a), "l"(b));
}

// ---------------------------------------------------------------- views
__global__ void views_kernel()
{
    int i = blockIdx.x * blockDim.x + threadIdx.x;
    if (i >= NV) return;
    double phi = (sqrt(5.0) - 1.0) / 2.0;
    double z   = (2.0 * (double)i + 1.0) / (double)NV - 1.0;
    double r2  = 1.0 - z * z;
    double r   = sqrt(r2 > 0.0 ? r2 : 0.0);
    double ang = ((2.0 * 3.14159265358979323846) * (double)i) * phi;
    float x  = (float)(r * cos(ang));
    float y  = (float)(r * sin(ang));
    float zf = (float)z;
    g_views[i * 3 + 0] = x;
    g_views[i * 3 + 1] = y;
    g_views[i * 3 + 2] = zf;
    g_vnorm[i] = sqrtf(x * x + y * y + zf * zf);
}

// ---------------------------------------------------------------- GEMM1: 128x256 tile, 8x16 microtile (FMA-bound)
__global__ __launch_bounds__(256, 1) void sgemm_bn_relu_w(
                              const float* __restrict__ W,
                              const float* __restrict__ Bmat, long strideB,
                              float* __restrict__ Cmat, long strideC,
                              int ncols,
                              const float* __restrict__ bias,
                              const float* __restrict__ bng, const float* __restrict__ bnb,
                              const float* __restrict__ bnm, const float* __restrict__ bnv)
{
    __shared__ __align__(16) float As[8][132];
    __shared__ __align__(16) float Bs[8][256];
    const int b    = blockIdx.z;
    const int row0 = blockIdx.y * 128;
    const int col0 = blockIdx.x * 256;
    const float* Bb = Bmat + (long)b * strideB;
    float* Cb = Cmat + (long)b * strideC;
    const int tid  = threadIdx.x;
    const int trow = tid >> 4;          // 0..15 -> 8 rows
    const int tcol = tid & 15;          // 0..15 -> cols tcol*4 + g*64, g=0..3

    // loaders
    const int a_r  = tid >> 1;          // 0..127
    const int a_kg = (tid & 1) * 4;     // 0 or 4
    const int b_k  = tid >> 5;          // 0..7
    const int b_c  = (tid & 31) * 8;    // 0..248
    const int b_col = col0 + b_c;

    unsigned long long acc[8][8];
#pragma unroll
    for (int i = 0; i < 8; i++)
#pragma unroll
        for (int j = 0; j < 8; j++) acc[i][j] = 0ULL;

    float4 aReg, bR0, bR1;
    aReg = *reinterpret_cast<const float4*>(&W[(row0 + a_r) * CCH + a_kg]);
    {
        const float* src = &Bb[(long)b_k * ncols + b_col];
        if (b_col + 7 < ncols) {
            bR0 = *reinterpret_cast<const float4*>(src);
            bR1 = *reinterpret_cast<const float4*>(src + 4);
        } else {
            bR0.x = (b_col + 0 < ncols) ? src[0] : 0.f;
            bR0.y = (b_col + 1 < ncols) ? src[1] : 0.f;
            bR0.z = (b_col + 2 < ncols) ? src[2] : 0.f;
            bR0.w = (b_col + 3 < ncols) ? src[3] : 0.f;
            bR1.x = (b_col + 4 < ncols) ? src[4] : 0.f;
            bR1.y = (b_col + 5 < ncols) ? src[5] : 0.f;
            bR1.z = (b_col + 6 < ncols) ? src[6] : 0.f;
            bR1.w = (b_col + 7 < ncols) ? src[7] : 0.f;
        }
    }

    for (int kc = 0; kc < CCH; kc += 8) {
        if (kc) __syncthreads();
        As[a_kg + 0][a_r] = aReg.x;
        As[a_kg + 1][a_r] = aReg.y;
        As[a_kg + 2][a_r] = aReg.z;
        As[a_kg + 3][a_r] = aReg.w;
        *reinterpret_cast<float4*>(&Bs[b_k][b_c])     = bR0;
        *reinterpret_cast<float4*>(&Bs[b_k][b_c + 4]) = bR1;
        __syncthreads();

        if (kc + 8 < CCH) {
            aReg = *reinterpret_cast<const float4*>(&W[(row0 + a_r) * CCH + kc + 8 + a_kg]);
            const float* src = &Bb[(long)(kc + 8 + b_k) * ncols + b_col];
            if (b_col + 7 < ncols) {
                bR0 = *reinterpret_cast<const float4*>(src);
                bR1 = *reinterpret_cast<const float4*>(src + 4);
            } else {
                bR0.x = (b_col + 0 < ncols) ? src[0] : 0.f;
                bR0.y = (b_col + 1 < ncols) ? src[1] : 0.f;
                bR0.z = (b_col + 2 < ncols) ? src[2] : 0.f;
                bR0.w = (b_col + 3 < ncols) ? src[3] : 0.f;
                bR1.x = (b_col + 4 < ncols) ? src[4] : 0.f;
                bR1.y = (b_col + 5 < ncols) ? src[5] : 0.f;
                bR1.z = (b_col + 6 < ncols) ? src[6] : 0.f;
                bR1.w = (b_col + 7 < ncols) ? src[7] : 0.f;
            }
        }

#pragma unroll
        for (int k = 0; k < 8; k++) {
            float4 a0 = *reinterpret_cast<const float4*>(&As[k][trow * 8]);
            float4 a1 = *reinterpret_cast<const float4*>(&As[k][trow * 8 + 4]);
            float4 b0 = *reinterpret_cast<const float4*>(&Bs[k][tcol * 4]);
            float4 b1 = *reinterpret_cast<const float4*>(&Bs[k][tcol * 4 + 64]);
            float4 b2 = *reinterpret_cast<const float4*>(&Bs[k][tcol * 4 + 128]);
            float4 b3 = *reinterpret_cast<const float4*>(&Bs[k][tcol * 4 + 192]);
            unsigned long long bb[8];
            bb[0] = pack2(b0.x, b0.y);
            bb[1] = pack2(b0.z, b0.w);
            bb[2] = pack2(b1.x, b1.y);
            bb[3] = pack2(b1.z, b1.w);
            bb[4] = pack2(b2.x, b2.y);
            bb[5] = pack2(b2.z, b2.w);
            bb[6] = pack2(b3.x, b3.y);
            bb[7] = pack2(b3.z, b3.w);
            float av[8] = {a0.x, a0.y, a0.z, a0.w, a1.x, a1.y, a1.z, a1.w};
#pragma unroll
            for (int i = 0; i < 8; i++) {
                unsigned long long aa = pack2(av[i], av[i]);
#pragma unroll
                for (int j = 0; j < 8; j++)
                    ffma2(acc[i][j], aa, bb[j]);
            }
        }
    }

#pragma unroll
    for (int i = 0; i < 8; i++) {
        int row = row0 + trow * 8 + i;
        float sc = bng[row] / sqrtf(bnv[row] + 1e-5f);
        float sh = (bias[row] - bnm[row]) * sc + bnb[row];
        float v[16];
#pragma unroll
        for (int j = 0; j < 8; j++) unpack2(acc[i][j], v[2 * j], v[2 * j + 1]);
#pragma unroll
        for (int g = 0; g < 4; g++) {
            int col = col0 + tcol * 4 + g * 64;
            float4 o;
            o.x = fmaxf(v[4 * g + 0] * sc + sh, 0.f);
            o.y = fmaxf(v[4 * g + 1] * sc + sh, 0.f);
            o.z = fmaxf(v[4 * g + 2] * sc + sh, 0.f);
            o.w = fmaxf(v[4 * g + 3] * sc + sh, 0.f);
            if (col + 3 < ncols) {
                *reinterpret_cast<float4*>(&Cb[(long)row * ncols + col]) = o;
            } else {
                if (col + 0 < ncols) Cb[(long)row * ncols + col + 0] = o.x;
                if (col + 1 < ncols) Cb[(long)row * ncols + col + 1] = o.y;
                if (col + 2 < ncols) Cb[(long)row * ncols + col + 2] = o.z;
                if (col + 3 < ncols) Cb[(long)row * ncols + col + 3] = o.w;
            }
        }
    }
}

// ---------------------------------------------------------------- GEMM2 (R4-proven 128x128)
__global__ __launch_bounds__(256, 2) void sgemm_bn_relu(
                              const float* __restrict__ W,
                              const float* __restrict__ Bmat, long strideB,
                              float* __restrict__ Cmat, long strideC,
                              int ncols,
                              const float* __restrict__ bias,
                              const float* __restrict__ bng, const float* __restrict__ bnb,
                              const float* __restrict__ bnm, const float* __restrict__ bnv)
{
    __shared__ __align__(16) float As[8][132];
    __shared__ __align__(16) float Bs[8][128];
    const int b    = blockIdx.z;
    const int row0 = blockIdx.y * 128;
    const int col0 = blockIdx.x * 128;
    const float* Bb = Bmat + (long)b * strideB;
    float* Cb = Cmat + (long)b * strideC;
    const int tid  = threadIdx.x;
    const int trow = tid >> 4;
    const int tcol = tid & 15;

    const int a_r  = tid >> 1;
    const int a_kg = (tid & 1) * 4;
    const int b_c  = (tid & 31) * 4;
    const int b_k  = tid >> 5;
    const int b_col = col0 + b_c;

    unsigned long long acc[8][4];
#pragma unroll
    for (int i = 0; i < 8; i++)
#pragma unroll
        for (int j = 0; j < 4; j++) acc[i][j] = 0ULL;

    float4 aReg, bReg;
    aReg = *reinterpret_cast<const float4*>(&W[(row0 + a_r) * CCH + a_kg]);
    if (b_col + 3 < ncols) {
        bReg = *reinterpret_cast<const float4*>(&Bb[(long)b_k * ncols + b_col]);
    } else {
        bReg.x = (b_col + 0 < ncols) ? Bb[(long)b_k * ncols + b_col + 0] : 0.f;
        bReg.y = (b_col + 1 < ncols) ? Bb[(long)b_k * ncols + b_col + 1] : 0.f;
        bReg.z = (b_col + 2 < ncols) ? Bb[(long)b_k * ncols + b_col + 2] : 0.f;
        bReg.w = (b_col + 3 < ncols) ? Bb[(long)b_k * ncols + b_col + 3] : 0.f;
    }

    for (int kc = 0; kc < CCH; kc += 8) {
        if (kc) __syncthreads();
        As[a_kg + 0][a_r] = aReg.x;
        As[a_kg + 1][a_r] = aReg.y;
        As[a_kg + 2][a_r] = aReg.z;
        As[a_kg + 3][a_r] = aReg.w;
        *reinterpret_cast<float4*>(&Bs[b_k][b_c]) = bReg;
        __syncthreads();

        if (kc + 8 < CCH) {
            aReg = *reinterpret_cast<const float4*>(&W[(row0 + a_r) * CCH + kc + 8 + a_kg]);
            if (b_col + 3 < ncols) {
                bReg = *reinterpret_cast<const float4*>(&Bb[(long)(kc + 8 + b_k) * ncols + b_col]);
            } else {
                bReg.x = (b_col + 0 < ncols) ? Bb[(long)(kc + 8 + b_k) * ncols + b_col + 0] : 0.f;
                bReg.y = (b_col + 1 < ncols) ? Bb[(long)(kc + 8 + b_k) * ncols + b_col + 1] : 0.f;
                bReg.z = (b_col + 2 < ncols) ? Bb[(long)(kc + 8 + b_k) * ncols + b_col + 2] : 0.f;
                bReg.w = (b_col + 3 < ncols) ? Bb[(long)(kc + 8 + b_k) * ncols + b_col + 3] : 0.f;
            }
        }

#pragma unroll
        for (int k = 0; k < 8; k++) {
            float4 a0 = *reinterpret_cast<const float4*>(&As[k][trow * 8]);
            float4 a1 = *reinterpret_cast<const float4*>(&As[k][trow * 8 + 4]);
            float4 b0 = *reinterpret_cast<const float4*>(&Bs[k][tcol * 4]);
            float4 b1 = *reinterpret_cast<const float4*>(&Bs[k][tcol * 4 + 64]);
            unsigned long long bb[4];
            bb[0] = pack2(b0.x, b0.y);
            bb[1] = pack2(b0.z, b0.w);
            bb[2] = pack2(b1.x, b1.y);
            bb[3] = pack2(b1.z, b1.w);
            float av[8] = {a0.x, a0.y, a0.z, a0.w, a1.x, a1.y, a1.z, a1.w};
#pragma unroll
            for (int i = 0; i < 8; i++) {
                unsigned long long aa = pack2(av[i], av[i]);
#pragma unroll
                for (int j = 0; j < 4; j++)
                    ffma2(acc[i][j], aa, bb[j]);
            }
        }
    }

#pragma unroll
    for (int i = 0; i < 8; i++) {
        int row = row0 + trow * 8 + i;
        float sc = bng[row] / sqrtf(bnv[row] + 1e-5f);
        float sh = (bias[row] - bnm[row]) * sc + bnb[row];
        float v[8];
#pragma unroll
        for (int j = 0; j < 4; j++) unpack2(acc[i][j], v[2 * j], v[2 * j + 1]);
#pragma unroll
        for (int g = 0; g < 2; g++) {
            int col = col0 + tcol * 4 + g * 64;
            float4 o;
            o.x = fmaxf(v[4 * g + 0] * sc + sh, 0.f);
            o.y = fmaxf(v[4 * g + 1] * sc + sh, 0.f);
            o.z = fmaxf(v[4 * g + 2] * sc + sh, 0.f);
            o.w = fmaxf(v[4 * g + 3] * sc + sh, 0.f);
            if (col + 3 < ncols) {
                *reinterpret_cast<float4*>(&Cb[(long)row * ncols + col]) = o;
            } else {
                if (col + 0 < ncols) Cb[(long)row * ncols + col + 0] = o.x;
                if (col + 1 < ncols) Cb[(long)row * ncols + col + 1] = o.y;
                if (col + 2 < ncols) Cb[(long)row * ncols + col + 2] = o.z;
                if (col + 3 < ncols) Cb[(long)row * ncols + col + 3] = o.w;
            }
        }
    }
}

// ---------------------------------------------------------------- graspable head (3-channel conv) + mask
__global__ void graspable_kernel(const float* __restrict__ w2, const float* __restrict__ b2,
                                 float* __restrict__ out)
{
    __shared__ float sw[3 * CCH];
    int tid = threadIdx.x;
    for (int i = tid; i < 3 * CCH; i += blockDim.x) sw[i] = w2[i];
    __syncthreads();
    int b = blockIdx.z;
    int n = blockIdx.x * blockDim.x + tid;
    if (n >= NPTS) return;
    const float* hc = g_h + (long)b * CCH * NPTS + n;
    float s0 = b2[0], s1 = b2[1], s2 = b2[2];
#pragma unroll 8
    for (int c = 0; c < CCH; c++) {
        float hv = hc[(long)c * NPTS];
        s0 += sw[c] * hv;
        s1 += sw[CCH + c] * hv;
        s2 += sw[2 * CCH + c] * hv;
    }
    out[O_OBJ + ((long)b * 2) * NPTS + n]     = s0;
    out[O_OBJ + ((long)b * 2 + 1) * NPTS + n] = s1;
    out[O_GRASP + (long)b * NPTS + n]         = s2;
    g_mask[b * NPTS + n] = (unsigned char)((s1 > s0) && (s2 > 0.1f));
}

// ---------------------------------------------------------------- FPS (R4 proven version)
#define FPS_T    256
#define FPS_NW   8
#define FPS_CAP  13312
#define FPS_RNG  79         // ceil(20000/256)
#define FPS_SMEM (FPS_CAP * 16)

__device__ __forceinline__ void argmax_redux(unsigned& u, int& mi)
{
    unsigned um;
    asm("redux.sync.max.u32 %0, %1, 0xffffffff;" : "=r"(um) : "r"(u));
    unsigned cand = (u == um) ? (unsigned)mi : 0x7fffffffu;
    unsigned bm;
    asm("redux.sync.min.u32 %0, %1, 0xffffffff;" : "=r"(bm) : "r"(cand));
    u = um; mi = (int)bm;
}

struct FpsShared {
    unsigned r_v[2][FPS_NW];
    int      r_i[2][FPS_NW];
};

__device__ __forceinline__ int block_argmax(unsigned u, int mi, FpsShared* sh,
                                            int lane, int w, int par)
{
    argmax_redux(u, mi);
    if (lane == 0) { sh->r_v[par][w] = u; sh->r_i[par][w] = mi; }
    __syncthreads();
    unsigned u2 = (lane < FPS_NW) ? sh->r_v[par][lane] : 0u;
    int mi2 = (lane < FPS_NW) ? sh->r_i[par][lane] : 0x7fffffff;
    argmax_redux(u2, mi2);
    return mi2;
}

template<int PPT>
__device__ void fps_reg_loop(const float* s_x, const float* s_y, const float* s_z,
                             const int* s_i, int total, int* inds,
                             FpsShared* sh, int tid, int lane, int w)
{
    float px[PPT], py[PPT], pz[PPT], dist[PPT];
#pragma unroll
    for (int j = 0; j < PPT; j++) {
        int ci = tid + j * FPS_T;
        bool ok = ci < total;
        px[j]   = ok ? s_x[ci] : 0.f;
        py[j]   = ok ? s_y[ci] : 0.f;
        pz[j]   = ok ? s_z[ci] : 0.f;
        dist[j] = ok ? 1e10f : -1.f;
    }

    int best = 0;
    int par = 0;
    for (int s = 0; s < NS; s++) {
        if (tid == 0) inds[s] = s_i[best];
        float lx = s_x[best], ly = s_y[best], lz = s_z[best];
        float mv = -0.5f; int mi = 0x7fffffff;
#pragma unroll
        for (int j = 0; j < PPT; j++) {
            float dx = px[j] - lx;
            float dy = py[j] - ly;
            float dz = pz[j] - lz;
            float d  = fmaf(dz, dz, fmaf(dy, dy, dx * dx));
            float nd = fminf(dist[j], d);
            dist[j] = nd;
            if (nd > mv) { mv = nd; mi = tid + j * FPS_T; }
        }
        unsigned u = (mi == 0x7fffffff) ? 0u : __float_as_uint(mv);
        best = block_argmax(u, mi, sh, lane, w, par);
        par ^= 1;
    }
}

template<int PPT>
__device__ void fps_smem_loop(const float* s_x, const float* s_y, const float* s_z,
                              const int* s_i, int total, int* inds,
                              FpsShared* sh, int tid, int lane, int w)
{
    float dist[PPT];
#pragma unroll
    for (int j = 0; j < PPT; j++)
        dist[j] = (tid + j * FPS_T < total) ? 1e10f : -1.f;

    int best = 0;
    int par = 0;
    for (int s = 0; s < NS; s++) {
        if (tid == 0) inds[s] = s_i[best];
        float lx = s_x[best], ly = s_y[best], lz = s_z[best];
        float mv = -0.5f; int mi = 0x7fffffff;
#pragma unroll
        for (int j = 0; j < PPT; j++) {
            int ci = tid + j * FPS_T;
            if (ci < total) {
                float dx = s_x[ci] - lx;
                float dy = s_y[ci] - ly;
                float dz = s_z[ci] - lz;
                float d  = fmaf(dz, dz, fmaf(dy, dy, dx * dx));
                float nd = fminf(dist[j], d);
                dist[j] = nd;
                if (nd > mv) { mv = nd; mi = ci; }
            }
        }
        unsigned u = (mi == 0x7fffffff) ? 0u : __float_as_uint(mv);
        best = block_argmax(u, mi, sh, lane, w, par);
        par ^= 1;
    }
}

__global__ __launch_bounds__(FPS_T, 1) void fps_kernel(const float* __restrict__ xyz)
{
    extern __shared__ unsigned char s_raw[];
    float* s_x = (float*)s_raw;
    float* s_y = s_x + FPS_CAP;
    float* s_z = s_y + FPS_CAP;
    int*   s_i = (int*)(s_z + FPS_CAP);

    __shared__ FpsShared sh;
    __shared__ int wsum[FPS_NW], woff[FPS_NW], s_total;

    const int b   = blockIdx.x;
    const int tid = threadIdx.x;
    const int lane = tid & 31, w = tid >> 5;
    const float* X = xyz + (long)b * NPTS * 3;
    const unsigned char* M = g_mask + b * NPTS;
    int* inds = g_inds + b * NS;

    int lo = tid * FPS_RNG;
    int hi = lo + FPS_RNG; if (hi > NPTS) hi = NPTS;
    if (lo > NPTS) lo = NPTS;
    int cnt = 0;
    for (int p = lo; p < hi; p++) cnt += M[p];

    int inc = cnt;
#pragma unroll
    for (int o = 1; o < 32; o <<= 1) {
        int v = __shfl_up_sync(0xffffffffu, inc, o);
        if (lane >= o) inc += v;
    }
    if (lane == 31) wsum[w] = inc;
    __syncthreads();
    if (tid < FPS_NW) {
        int v = wsum[tid];
        int iv = v;
#pragma unroll
        for (int o = 1; o < FPS_NW; o <<= 1) {
            int u = __shfl_up_sync(0x000000ffu, iv, o);
            if (tid >= o) iv += u;
        }
        woff[tid] = iv - v;
        if (tid == FPS_NW - 1) s_total = iv;
    }
    __syncthreads();
    const int total = s_total;
    int excl = woff[w] + (inc - cnt);

    if (total == 0) {
        for (int s = tid; s < NS; s += FPS_T) inds[s] = 0;
        return;
    }

    if (total <= FPS_CAP) {
        int pos = excl;
        for (int p = lo; p < hi; p++) {
            if (M[p]) {
                s_x[pos] = X[p * 3 + 0];
                s_y[pos] = X[p * 3 + 1];
                s_z[pos] = X[p * 3 + 2];
                s_i[pos] = p;
                pos++;
            }
        }
        __syncthreads();

        if      (total <= FPS_T * 6)  fps_reg_loop<6>  (s_x, s_y, s_z, s_i, total, inds, &sh, tid, lane, w);
        else if (total <= FPS_T * 12) fps_reg_loop<12> (s_x, s_y, s_z, s_i, total, inds, &sh, tid, lane, w);
        else if (total <= FPS_T * 18) fps_reg_loop<18> (s_x, s_y, s_z, s_i, total, inds, &sh, tid, lane, w);
        else if (total <= FPS_T * 24) fps_reg_loop<24> (s_x, s_y, s_z, s_i, total, inds, &sh, tid, lane, w);
        else if (total <= FPS_T * 36) fps_smem_loop<36>(s_x, s_y, s_z, s_i, total, inds, &sh, tid, lane, w);
        else                          fps_smem_loop<52>(s_x, s_y, s_z, s_i, total, inds, &sh, tid, lane, w);
    } else {
        float* dist = (float*)s_raw;
        for (int p = tid; p < NPTS; p += FPS_T)
            dist[p] = M[p] ? 1e10f : -1.f;
        __syncthreads();
        unsigned u = 0; int mi = 0x7fffffff;
        for (int p = tid; p < NPTS; p += FPS_T)
            if (M[p]) { if (p < mi) { u = 1u; mi = p; } }
        int best = block_argmax(u, mi, &sh, lane, w, 0);
        int par = 1;
        for (int s = 0; s < NS; s++) {
            if (tid == 0) inds[s] = best;
            float lx = X[best * 3 + 0], ly = X[best * 3 + 1], lz = X[best * 3 + 2];
            unsigned mu = 0u; int mmi = 0x7fffffff;
            for (int p = tid; p < NPTS; p += FPS_T) {
                float dv = dist[p];
                if (dv >= 0.f) {
                    float dx = X[p * 3 + 0] - lx;
                    float dy = X[p * 3 + 1] - ly;
                    float dz = X[p * 3 + 2] - lz;
                    float d  = fmaf(dz, dz, fmaf(dy, dy, dx * dx));
                    dv = fminf(dv, d);
                    dist[p] = dv;
                    unsigned ub = __float_as_uint(dv);
                    if (ub > mu) { mu = ub; mmi = p; }
                }
            }
            best = block_argmax(mu, mmi, &sh, lane, w, par & 1);
            par ^= 1;
        }
    }
}

// ---------------------------------------------------------------- gathers
__global__ void gather_small(const float* __restrict__ xyz, float* __restrict__ out)
{
    int idx = blockIdx.x * blockDim.x + threadIdx.x;
    if (idx >= BB * NS) return;
    int b = idx >> 10;
    int ind = g_inds[idx];
    const float* p = xyz + ((long)b * NPTS + ind) * 3;
    out[O_GXYZ + (long)idx * 3 + 0] = p[0];
    out[O_GXYZ + (long)idx * 3 + 1] = p[1];
    out[O_GXYZ + (long)idx * 3 + 2] = p[2];
    out[O_GIND + idx] = (float)ind;
    out[O_FP2 + idx]  = out[O_GRASP + (long)b * NPTS + ind];
}

__global__ void gather_feat(const float* __restrict__ feat, float* __restrict__ out)
{
    long gid = (long)blockIdx.x * blockDim.x + threadIdx.x;
    if (gid >= (long)BB * CCH * NS) return;
    int s = (int)(gid & (NS - 1));
    int c = (int)((gid >> 10) & 255);
    int b = (int)(gid >> 18);
    int ind = g_inds[b * NS + s];
    out[O_GFEAT + gid] = feat[((long)b * CCH + c) * NPTS + ind];
}

// ---------------------------------------------------------------- final: vp_xyz, top view, rot
__global__ void final_kernel(const float* __restrict__ c2w, const float* __restrict__ c2b,
                             float* __restrict__ out)
{
    __shared__ float sw[3 * CCH];
    __shared__ float svx[NV], svy[NV], svz[NV], svn[NV];
    int tid = threadIdx.x;
    for (int i = tid; i < 3 * CCH; i += blockDim.x) sw[i] = c2w[i];
    for (int i = tid; i < NV; i += blockDim.x) {
        svx[i] = g_views[i * 3 + 0];
        svy[i] = g_views[i * 3 + 1];
        svz[i] = g_views[i * 3 + 2];
        svn[i] = g_vnorm[i];
    }
    __syncthreads();
    int idx = blockIdx.x * blockDim.x + tid;
    if (idx >= BB * NS) return;
    int b = idx >> 10, s = idx & (NS - 1);
    const float* F = g_f + (long)b * CCH * NS + s;
    float v0 = c2b[0], v1 = c2b[1], v2 = c2b[2];
#pragma unroll 8
    for (int c = 0; c < CCH; c++) {
        float f = F[(long)c * NS];
        v0 += sw[c] * f;
        v1 += sw[CCH + c] * f;
        v2 += sw[2 * CCH + c] * f;
    }
    out[O_VPXYZ + (long)idx * 3 + 0] = v0;
    out[O_VPXYZ + (long)idx * 3 + 1] = v1;
    out[O_VPXYZ + (long)idx * 3 + 2] = v2;

    float pn = sqrtf(v0 * v0 + v1 * v1 + v2 * v2);
    float bs = -3.4e38f; int bi = 0;
    for (int v = 0; v < NV; v++) {
        float dot = svx[v] * v0 + svy[v] * v1 + svz[v] * v2;
        float den = fmaxf(svn[v] * pn, 1e-8f);
        float scv = dot / den;
        if (scv > bs) { bs = scv; bi = v; }
    }
    out[O_TOPV + idx] = (float)bi;

    float tx = -v0, ty = -v1, tz = -v2;
    float ayx = -ty, ayy = tx, ayz = 0.f;
    float ny = sqrtf(ayx * ayx + ayy * ayy + ayz * ayz);
    if (ny == 0.f) { ayx = 0.f; ayy = 1.f; ayz = 0.f; }
    float nx = sqrtf(tx * tx + ty * ty + tz * tz);
    float ax0 = tx / nx, ax1 = ty / nx, ax2 = tz / nx;
    float ny2 = sqrtf(ayx * ayx + ayy * ayy + ayz * ayz);
    float ay0 = ayx / ny2, ay1 = ayy / ny2, ay2 = ayz / ny2;
    float az0 = ax1 * ay2 - ax2 * ay1;
    float az1 = ax2 * ay0 - ax0 * ay2;
    float az2 = ax0 * ay1 - ax1 * ay0;
    float* R = out + O_VPROT + (long)idx * 9;
    R[0] = ax0; R[1] = ay0; R[2] = az0;
    R[3] = ax1; R[4] = ay1; R[5] = az1;
    R[6] = ax2; R[7] = ay2; R[8] = az2;
}

// ---------------------------------------------------------------- launch
extern "C" void kernel_launch(void* const* d_in, const int* in_sizes, int n_in,
                              void* d_out, int out_size)
{
    const float* seed_xyz  = (const float*)d_in[0];
    const float* seed_feat = (const float*)d_in[1];
    const float* gh_w1     = (const float*)d_in[2];
    const float* gh_b1     = (const float*)d_in[3];
    const float* gh_bn_g   = (const float*)d_in[4];
    const float* gh_bn_b   = (const float*)d_in[5];
    const float* gh_bn_m   = (const float*)d_in[6];
    const float* gh_bn_v   = (const float*)d_in[7];
    const float* gh_w2     = (const float*)d_in[8];
    const float* gh_b2     = (const float*)d_in[9];
    const float* c1_w      = (const float*)d_in[10];
    const float* c1_b      = (const float*)d_in[11];
    const float* bn1_g     = (const float*)d_in[12];
    const float* bn1_b     = (const float*)d_in[13];
    const float* bn1_m     = (const float*)d_in[14];
    const float* bn1_v     = (const float*)d_in[15];
    const float* c2_w      = (const float*)d_in[16];
    const float* c2_b      = (const float*)d_in[17];
    float* out = (float*)d_out;

    cudaFuncSetAttribute(fps_kernel, cudaFuncAttributeMaxDynamicSharedMemorySize, FPS_SMEM);

    float *hptr = 0, *fptr = 0;
    cudaGetSymbolAddress((void**)&hptr, g_h);
    cudaGetSymbolAddress((void**)&fptr, g_f);

    views_kernel<<<1, 320>>>();

    // GEMM1: wide FMA-bound tile (128x256)
    sgemm_bn_relu_w<<<dim3((NPTS + 255) / 256, 2, BB), 256>>>(
        gh_w1, seed_feat, (long)CCH * NPTS, hptr, (long)CCH * NPTS, NPTS,
        gh_b1, gh_bn_g, gh_bn_b, gh_bn_m, gh_bn_v);

    graspable_kernel<<<dim3((NPTS + 255) / 256, 1, BB), 256>>>(gh_w2, gh_b2, out);

    fps_kernel<<<BB, FPS_T, FPS_SMEM>>>(seed_xyz);

    gather_small<<<(BB * NS + 255) / 256, 256>>>(seed_xyz, out);
    gather_feat<<<(BB * CCH * NS + 255) / 256, 256>>>(seed_feat, out);

    sgemm_bn_relu<<<dim3(NS / 128, 2, BB), 256>>>(
        c1_w, out + O_GFEAT, (long)CCH * NS, fptr, (long)CCH * NS, NS,
        c1_b, bn1_g, bn1_b, bn1_m, bn1_v);

    final_kernel<<<(BB * NS + 255) / 256, 256>>>(c2_w, c2_b, out);
}

// round 8
// speedup vs baseline: 1.2132x; 1.2132x over previous
#include <cuda_runtime.h>
#include <math.h>

#define BB   4
#define NPTS 20000
#define CCH  256
#define NS   1024
#define NV   300

// output packing offsets (float32 elements, tuple order)
#define O_OBJ   0L        // (4,2,20000)  160000
#define O_GRASP 160000L   // (4,20000)     80000
#define O_GXYZ  240000L   // (4,1024,3)    12288
#define O_GIND  252288L   // (4,1024)       4096
#define O_GFEAT 256384L   // (4,256,1024) 1048576
#define O_FP2   1304960L  // (4,1024)       4096
#define O_VPXYZ 1309056L  // (4,1024,3)    12288
#define O_TOPV  1321344L  // (4,1024)       4096
#define O_VPROT 1325440L  // (4,1024,3,3)  36864
// total = 1362304

__device__ float g_part[BB * 2 * 3 * NPTS]; // per-half graspable partials (1.9MB)
__device__ float g_f[BB * CCH * NS];        // second-stage activations
__device__ unsigned char g_mask[BB * NPTS];
__device__ int   g_inds[BB * NS];
__device__ float g_views[NV * 3];
__device__ float g_vnorm[NV];

// ---------------------------------------------------------------- packed f32x2 helpers
__device__ __forceinline__ unsigned long long pack2(float lo, float hi)
{
    unsigned long long r;
    asm("mov.b64 %0, {%1, %2};" : "=l"(r) : "f"(lo), "f"(hi));
    return r;
}
__device__ __forceinline__ void unpack2(unsigned long long v, float& lo, float& hi)
{
    asm("mov.b64 {%0, %1}, %2;" : "=f"(lo), "=f"(hi) : "l"(v));
}
__device__ __forceinline__ void ffma2(unsigned long long& d, unsigned long long a, unsigned long long b)
{
    asm("fma.rn.f32x2 %0, %1, %2, %0;" : "+l"(d) : "l"(a), "l"(b));
}

// ---------------------------------------------------------------- views
__global__ void views_kernel()
{
    int i = blockIdx.x * blockDim.x + threadIdx.x;
    if (i >= NV) return;
    double phi = (sqrt(5.0) - 1.0) / 2.0;
    double z   = (2.0 * (double)i + 1.0) / (double)NV - 1.0;
    double r2  = 1.0 - z * z;
    double r   = sqrt(r2 > 0.0 ? r2 : 0.0);
    double ang = ((2.0 * 3.14159265358979323846) * (double)i) * phi;
    float x  = (float)(r * cos(ang));
    float y  = (float)(r * sin(ang));
    float zf = (float)z;
    g_views[i * 3 + 0] = x;
    g_views[i * 3 + 1] = y;
    g_views[i * 3 + 2] = zf;
    g_vnorm[i] = sqrtf(x * x + y * y + zf * zf);
}

// ---------------------------------------------------------------- GEMM1 (R4 mainloop) + fused graspable partial epilogue
// h = relu(bn(W@feat)) kept in registers; CTA writes 3-channel dot partials only.
__global__ __launch_bounds__(256, 2) void gemm1_fused(
                              const float* __restrict__ W,
                              const float* __restrict__ Feat,
                              const float* __restrict__ bias,
                              const float* __restrict__ bng, const float* __restrict__ bnb,
                              const float* __restrict__ bnm, const float* __restrict__ bnv,
                              const float* __restrict__ w2)
{
    __shared__ __align__(16) float As[8][132];
    __shared__ __align__(16) float Bs[8][128];
    __shared__ float sw[3 * CCH];
    __shared__ float pr[16][3][128];
    const int b    = blockIdx.z;
    const int half = blockIdx.y;
    const int row0 = half * 128;
    const int col0 = blockIdx.x * 128;
    const float* Bb = Feat + (long)b * CCH * NPTS;
    const int tid  = threadIdx.x;
    const int trow = tid >> 4;
    const int tcol = tid & 15;
    const int ncols = NPTS;

    for (int i = tid; i < 3 * CCH; i += 256) sw[i] = w2[i];

    const int a_r  = tid >> 1;
    const int a_kg = (tid & 1) * 4;
    const int b_c  = (tid & 31) * 4;
    const int b_k  = tid >> 5;
    const int b_col = col0 + b_c;

    unsigned long long acc[8][4];
#pragma unroll
    for (int i = 0; i < 8; i++)
#pragma unroll
        for (int j = 0; j < 4; j++) acc[i][j] = 0ULL;

    float4 aReg, bReg;
    aReg = *reinterpret_cast<const float4*>(&W[(row0 + a_r) * CCH + a_kg]);
    if (b_col + 3 < ncols) {
        bReg = *reinterpret_cast<const float4*>(&Bb[(long)b_k * ncols + b_col]);
    } else {
        bReg.x = (b_col + 0 < ncols) ? Bb[(long)b_k * ncols + b_col + 0] : 0.f;
        bReg.y = (b_col + 1 < ncols) ? Bb[(long)b_k * ncols + b_col + 1] : 0.f;
        bReg.z = (b_col + 2 < ncols) ? Bb[(long)b_k * ncols + b_col + 2] : 0.f;
        bReg.w = (b_col + 3 < ncols) ? Bb[(long)b_k * ncols + b_col + 3] : 0.f;
    }

    for (int kc = 0; kc < CCH; kc += 8) {
        if (kc) __syncthreads();
        As[a_kg + 0][a_r] = aReg.x;
        As[a_kg + 1][a_r] = aReg.y;
        As[a_kg + 2][a_r] = aReg.z;
        As[a_kg + 3][a_r] = aReg.w;
        *reinterpret_cast<float4*>(&Bs[b_k][b_c]) = bReg;
        __syncthreads();

        if (kc + 8 < CCH) {
            aReg = *reinterpret_cast<const float4*>(&W[(row0 + a_r) * CCH + kc + 8 + a_kg]);
            if (b_col + 3 < ncols) {
                bReg = *reinterpret_cast<const float4*>(&Bb[(long)(kc + 8 + b_k) * ncols + b_col]);
            } else {
                bReg.x = (b_col + 0 < ncols) ? Bb[(long)(kc + 8 + b_k) * ncols + b_col + 0] : 0.f;
                bReg.y = (b_col + 1 < ncols) ? Bb[(long)(kc + 8 + b_k) * ncols + b_col + 1] : 0.f;
                bReg.z = (b_col + 2 < ncols) ? Bb[(long)(kc + 8 + b_k) * ncols + b_col + 2] : 0.f;
                bReg.w = (b_col + 3 < ncols) ? Bb[(long)(kc + 8 + b_k) * ncols + b_col + 3] : 0.f;
            }
        }

#pragma unroll
        for (int k = 0; k < 8; k++) {
            float4 a0 = *reinterpret_cast<const float4*>(&As[k][trow * 8]);
            float4 a1 = *reinterpret_cast<const float4*>(&As[k][trow * 8 + 4]);
            float4 b0 = *reinterpret_cast<const float4*>(&Bs[k][tcol * 4]);
            float4 b1 = *reinterpret_cast<const float4*>(&Bs[k][tcol * 4 + 64]);
            unsigned long long bb[4];
            bb[0] = pack2(b0.x, b0.y);
            bb[1] = pack2(b0.z, b0.w);
            bb[2] = pack2(b1.x, b1.y);
            bb[3] = pack2(b1.z, b1.w);
            float av[8] = {a0.x, a0.y, a0.z, a0.w, a1.x, a1.y, a1.z, a1.w};
#pragma unroll
            for (int i = 0; i < 8; i++) {
                unsigned long long aa = pack2(av[i], av[i]);
#pragma unroll
                for (int j = 0; j < 4; j++)
                    ffma2(acc[i][j], aa, bb[j]);
            }
        }
    }

    // fused epilogue: h in registers -> 3-channel partial dots
    float p0[8], p1[8], p2[8];
#pragma unroll
    for (int j = 0; j < 8; j++) { p0[j] = 0.f; p1[j] = 0.f; p2[j] = 0.f; }
#pragma unroll
    for (int i = 0; i < 8; i++) {
        int row = row0 + trow * 8 + i;
        float sc = bng[row] / sqrtf(bnv[row] + 1e-5f);
        float sh = (bias[row] - bnm[row]) * sc + bnb[row];
        float w0 = sw[row], w1 = sw[CCH + row], wv = sw[2 * CCH + row];
        float v[8];
#pragma unroll
        for (int j = 0; j < 4; j++) unpack2(acc[i][j], v[2 * j], v[2 * j + 1]);
#pragma unroll
        for (int j = 0; j < 8; j++) {
            float h = fmaxf(v[j] * sc + sh, 0.f);
            p0[j] = fmaf(w0, h, p0[j]);
            p1[j] = fmaf(w1, h, p1[j]);
            p2[j] = fmaf(wv, h, p2[j]);
        }
    }
    __syncthreads();  // protect Bs/As reuse boundary & order pr writes
#pragma unroll
    for (int g = 0; g < 2; g++) {
#pragma unroll
        for (int j = 0; j < 4; j++) {
            int c = tcol * 4 + g * 64 + j;
            pr[trow][0][c] = p0[4 * g + j];
            pr[trow][1][c] = p1[4 * g + j];
            pr[trow][2][c] = p2[4 * g + j];
        }
    }
    __syncthreads();
    for (int t = tid; t < 384; t += 256) {
        int ch = t >> 7, c = t & 127;
        float s = 0.f;
#pragma unroll
        for (int g = 0; g < 16; g++) s += pr[g][ch][c];
        int gcol = col0 + c;
        if (gcol < NPTS)
            g_part[(((long)b * 2 + half) * 3 + ch) * NPTS + gcol] = s;
    }
}

// ---------------------------------------------------------------- combine halves -> obj/grasp/mask
__global__ void graspable_combine(const float* __restrict__ b2, float* __restrict__ out)
{
    int b = blockIdx.z;
    int n = blockIdx.x * blockDim.x + threadIdx.x;
    if (n >= NPTS) return;
    const float* P0 = g_part + ((long)b * 2 + 0) * 3 * NPTS;
    const float* P1 = g_part + ((long)b * 2 + 1) * 3 * NPTS;
    float s0 = b2[0] + P0[0 * NPTS + n] + P1[0 * NPTS + n];
    float s1 = b2[1] + P0[1 * NPTS + n] + P1[1 * NPTS + n];
    float s2 = b2[2] + P0[2 * NPTS + n] + P1[2 * NPTS + n];
    out[O_OBJ + ((long)b * 2) * NPTS + n]     = s0;
    out[O_OBJ + ((long)b * 2 + 1) * NPTS + n] = s1;
    out[O_GRASP + (long)b * NPTS + n]         = s2;
    g_mask[b * NPTS + n] = (unsigned char)((s1 > s0) && (s2 > 0.1f));
}

// ---------------------------------------------------------------- GEMM2 (R4-proven 128x128)
__global__ __launch_bounds__(256, 2) void sgemm_bn_relu(
                              const float* __restrict__ W,
                              const float* __restrict__ Bmat, long strideB,
                              float* __restrict__ Cmat, long strideC,
                              int ncols,
                              const float* __restrict__ bias,
                              const float* __restrict__ bng, const float* __restrict__ bnb,
                              const float* __restrict__ bnm, const float* __restrict__ bnv)
{
    __shared__ __align__(16) float As[8][132];
    __shared__ __align__(16) float Bs[8][128];
    const int b    = blockIdx.z;
    const int row0 = blockIdx.y * 128;
    const int col0 = blockIdx.x * 128;
    const float* Bb = Bmat + (long)b * strideB;
    float* Cb = Cmat + (long)b * strideC;
    const int tid  = threadIdx.x;
    const int trow = tid >> 4;
    const int tcol = tid & 15;

    const int a_r  = tid >> 1;
    const int a_kg = (tid & 1) * 4;
    const int b_c  = (tid & 31) * 4;
    const int b_k  = tid >> 5;
    const int b_col = col0 + b_c;

    unsigned long long acc[8][4];
#pragma unroll
    for (int i = 0; i < 8; i++)
#pragma unroll
        for (int j = 0; j < 4; j++) acc[i][j] = 0ULL;

    float4 aReg, bReg;
    aReg = *reinterpret_cast<const float4*>(&W[(row0 + a_r) * CCH + a_kg]);
    if (b_col + 3 < ncols) {
        bReg = *reinterpret_cast<const float4*>(&Bb[(long)b_k * ncols + b_col]);
    } else {
        bReg.x = (b_col + 0 < ncols) ? Bb[(long)b_k * ncols + b_col + 0] : 0.f;
        bReg.y = (b_col + 1 < ncols) ? Bb[(long)b_k * ncols + b_col + 1] : 0.f;
        bReg.z = (b_col + 2 < ncols) ? Bb[(long)b_k * ncols + b_col + 2] : 0.f;
        bReg.w = (b_col + 3 < ncols) ? Bb[(long)b_k * ncols + b_col + 3] : 0.f;
    }

    for (int kc = 0; kc < CCH; kc += 8) {
        if (kc) __syncthreads();
        As[a_kg + 0][a_r] = aReg.x;
        As[a_kg + 1][a_r] = aReg.y;
        As[a_kg + 2][a_r] = aReg.z;
        As[a_kg + 3][a_r] = aReg.w;
        *reinterpret_cast<float4*>(&Bs[b_k][b_c]) = bReg;
        __syncthreads();

        if (kc + 8 < CCH) {
            aReg = *reinterpret_cast<const float4*>(&W[(row0 + a_r) * CCH + kc + 8 + a_kg]);
            if (b_col + 3 < ncols) {
                bReg = *reinterpret_cast<const float4*>(&Bb[(long)(kc + 8 + b_k) * ncols + b_col]);
            } else {
                bReg.x = (b_col + 0 < ncols) ? Bb[(long)(kc + 8 + b_k) * ncols + b_col + 0] : 0.f;
                bReg.y = (b_col + 1 < ncols) ? Bb[(long)(kc + 8 + b_k) * ncols + b_col + 1] : 0.f;
                bReg.z = (b_col + 2 < ncols) ? Bb[(long)(kc + 8 + b_k) * ncols + b_col + 2] : 0.f;
                bReg.w = (b_col + 3 < ncols) ? Bb[(long)(kc + 8 + b_k) * ncols + b_col + 3] : 0.f;
            }
        }

#pragma unroll
        for (int k = 0; k < 8; k++) {
            float4 a0 = *reinterpret_cast<const float4*>(&As[k][trow * 8]);
            float4 a1 = *reinterpret_cast<const float4*>(&As[k][trow * 8 + 4]);
            float4 b0 = *reinterpret_cast<const float4*>(&Bs[k][tcol * 4]);
            float4 b1 = *reinterpret_cast<const float4*>(&Bs[k][tcol * 4 + 64]);
            unsigned long long bb[4];
            bb[0] = pack2(b0.x, b0.y);
            bb[1] = pack2(b0.z, b0.w);
            bb[2] = pack2(b1.x, b1.y);
            bb[3] = pack2(b1.z, b1.w);
            float av[8] = {a0.x, a0.y, a0.z, a0.w, a1.x, a1.y, a1.z, a1.w};
#pragma unroll
            for (int i = 0; i < 8; i++) {
                unsigned long long aa = pack2(av[i], av[i]);
#pragma unroll
                for (int j = 0; j < 4; j++)
                    ffma2(acc[i][j], aa, bb[j]);
            }
        }
    }

#pragma unroll
    for (int i = 0; i < 8; i++) {
        int row = row0 + trow * 8 + i;
        float sc = bng[row] / sqrtf(bnv[row] + 1e-5f);
        float sh = (bias[row] - bnm[row]) * sc + bnb[row];
        float v[8];
#pragma unroll
        for (int j = 0; j < 4; j++) unpack2(acc[i][j], v[2 * j], v[2 * j + 1]);
#pragma unroll
        for (int g = 0; g < 2; g++) {
            int col = col0 + tcol * 4 + g * 64;
            float4 o;
            o.x = fmaxf(v[4 * g + 0] * sc + sh, 0.f);
            o.y = fmaxf(v[4 * g + 1] * sc + sh, 0.f);
            o.z = fmaxf(v[4 * g + 2] * sc + sh, 0.f);
            o.w = fmaxf(v[4 * g + 3] * sc + sh, 0.f);
            if (col + 3 < ncols) {
                *reinterpret_cast<float4*>(&Cb[(long)row * ncols + col]) = o;
            } else {
                if (col + 0 < ncols) Cb[(long)row * ncols + col + 0] = o.x;
                if (col + 1 < ncols) Cb[(long)row * ncols + col + 1] = o.y;
                if (col + 2 < ncols) Cb[(long)row * ncols + col + 2] = o.z;
                if (col + 3 < ncols) Cb[(long)row * ncols + col + 3] = o.w;
            }
        }
    }
}

// ---------------------------------------------------------------- FPS (R4 proven version)
#define FPS_T    256
#define FPS_NW   8
#define FPS_CAP  13312
#define FPS_RNG  79         // ceil(20000/256)
#define FPS_SMEM (FPS_CAP * 16)

__device__ __forceinline__ void argmax_redux(unsigned& u, int& mi)
{
    unsigned um;
    asm("redux.sync.max.u32 %0, %1, 0xffffffff;" : "=r"(um) : "r"(u));
    unsigned cand = (u == um) ? (unsigned)mi : 0x7fffffffu;
    unsigned bm;
    asm("redux.sync.min.u32 %0, %1, 0xffffffff;" : "=r"(bm) : "r"(cand));
    u = um; mi = (int)bm;
}

struct FpsShared {
    unsigned r_v[2][FPS_NW];
    int      r_i[2][FPS_NW];
};

__device__ __forceinline__ int block_argmax(unsigned u, int mi, FpsShared* sh,
                                            int lane, int w, int par)
{
    argmax_redux(u, mi);
    if (lane == 0) { sh->r_v[par][w] = u; sh->r_i[par][w] = mi; }
    __syncthreads();
    unsigned u2 = (lane < FPS_NW) ? sh->r_v[par][lane] : 0u;
    int mi2 = (lane < FPS_NW) ? sh->r_i[par][lane] : 0x7fffffff;
    argmax_redux(u2, mi2);
    return mi2;
}

template<int PPT>
__device__ void fps_reg_loop(const float* s_x, const float* s_y, const float* s_z,
                             const int* s_i, int total, int* inds,
                             FpsShared* sh, int tid, int lane, int w)
{
    float px[PPT], py[PPT], pz[PPT], dist[PPT];
#pragma unroll
    for (int j = 0; j < PPT; j++) {
        int ci = tid + j * FPS_T;
        bool ok = ci < total;
        px[j]   = ok ? s_x[ci] : 0.f;
        py[j]   = ok ? s_y[ci] : 0.f;
        pz[j]   = ok ? s_z[ci] : 0.f;
        dist[j] = ok ? 1e10f : -1.f;
    }

    int best = 0;
    int par = 0;
    for (int s = 0; s < NS; s++) {
        if (tid == 0) inds[s] = s_i[best];
        float lx = s_x[best], ly = s_y[best], lz = s_z[best];
        float mv = -0.5f; int mi = 0x7fffffff;
#pragma unroll
        for (int j = 0; j < PPT; j++) {
            float dx = px[j] - lx;
            float dy = py[j] - ly;
            float dz = pz[j] - lz;
            float d  = fmaf(dz, dz, fmaf(dy, dy, dx * dx));
            float nd = fminf(dist[j], d);
            dist[j] = nd;
            if (nd > mv) { mv = nd; mi = tid + j * FPS_T; }
        }
        unsigned u = (mi == 0x7fffffff) ? 0u : __float_as_uint(mv);
        best = block_argmax(u, mi, sh, lane, w, par);
        par ^= 1;
    }
}

template<int PPT>
__device__ void fps_smem_loop(const float* s_x, const float* s_y, const float* s_z,
                              const int* s_i, int total, int* inds,
                              FpsShared* sh, int tid, int lane, int w)
{
    float dist[PPT];
#pragma unroll
    for (int j = 0; j < PPT; j++)
        dist[j] = (tid + j * FPS_T < total) ? 1e10f : -1.f;

    int best = 0;
    int par = 0;
    for (int s = 0; s < NS; s++) {
        if (tid == 0) inds[s] = s_i[best];
        float lx = s_x[best], ly = s_y[best], lz = s_z[best];
        float mv = -0.5f; int mi = 0x7fffffff;
#pragma unroll
        for (int j = 0; j < PPT; j++) {
            int ci = tid + j * FPS_T;
            if (ci < total) {
                float dx = s_x[ci] - lx;
                float dy = s_y[ci] - ly;
                float dz = s_z[ci] - lz;
                float d  = fmaf(dz, dz, fmaf(dy, dy, dx * dx));
                float nd = fminf(dist[j], d);
                dist[j] = nd;
                if (nd > mv) { mv = nd; mi = ci; }
            }
        }
        unsigned u = (mi == 0x7fffffff) ? 0u : __float_as_uint(mv);
        best = block_argmax(u, mi, sh, lane, w, par);
        par ^= 1;
    }
}

__global__ __launch_bounds__(FPS_T, 1) void fps_kernel(const float* __restrict__ xyz)
{
    extern __shared__ unsigned char s_raw[];
    float* s_x = (float*)s_raw;
    float* s_y = s_x + FPS_CAP;
    float* s_z = s_y + FPS_CAP;
    int*   s_i = (int*)(s_z + FPS_CAP);

    __shared__ FpsShared sh;
    __shared__ int wsum[FPS_NW], woff[FPS_NW], s_total;

    const int b   = blockIdx.x;
    const int tid = threadIdx.x;
    const int lane = tid & 31, w = tid >> 5;
    const float* X = xyz + (long)b * NPTS * 3;
    const unsigned char* M = g_mask + b * NPTS;
    int* inds = g_inds + b * NS;

    int lo = tid * FPS_RNG;
    int hi = lo + FPS_RNG; if (hi > NPTS) hi = NPTS;
    if (lo > NPTS) lo = NPTS;
    int cnt = 0;
    for (int p = lo; p < hi; p++) cnt += M[p];

    int inc = cnt;
#pragma unroll
    for (int o = 1; o < 32; o <<= 1) {
        int v = __shfl_up_sync(0xffffffffu, inc, o);
        if (lane >= o) inc += v;
    }
    if (lane == 31) wsum[w] = inc;
    __syncthreads();
    if (tid < FPS_NW) {
        int v = wsum[tid];
        int iv = v;
#pragma unroll
        for (int o = 1; o < FPS_NW; o <<= 1) {
            int u = __shfl_up_sync(0x000000ffu, iv, o);
            if (tid >= o) iv += u;
        }
        woff[tid] = iv - v;
        if (tid == FPS_NW - 1) s_total = iv;
    }
    __syncthreads();
    const int total = s_total;
    int excl = woff[w] + (inc - cnt);

    if (total == 0) {
        for (int s = tid; s < NS; s += FPS_T) inds[s] = 0;
        return;
    }

    if (total <= FPS_CAP) {
        int pos = excl;
        for (int p = lo; p < hi; p++) {
            if (M[p]) {
                s_x[pos] = X[p * 3 + 0];
                s_y[pos] = X[p * 3 + 1];
                s_z[pos] = X[p * 3 + 2];
                s_i[pos] = p;
                pos++;
            }
        }
        __syncthreads();

        if      (total <= FPS_T * 6)  fps_reg_loop<6>  (s_x, s_y, s_z, s_i, total, inds, &sh, tid, lane, w);
        else if (total <= FPS_T * 12) fps_reg_loop<12> (s_x, s_y, s_z, s_i, total, inds, &sh, tid, lane, w);
        else if (total <= FPS_T * 18) fps_reg_loop<18> (s_x, s_y, s_z, s_i, total, inds, &sh, tid, lane, w);
        else if (total <= FPS_T * 24) fps_reg_loop<24> (s_x, s_y, s_z, s_i, total, inds, &sh, tid, lane, w);
        else if (total <= FPS_T * 36) fps_smem_loop<36>(s_x, s_y, s_z, s_i, total, inds, &sh, tid, lane, w);
        else                          fps_smem_loop<52>(s_x, s_y, s_z, s_i, total, inds, &sh, tid, lane, w);
    } else {
        float* dist = (float*)s_raw;
        for (int p = tid; p < NPTS; p += FPS_T)
            dist[p] = M[p] ? 1e10f : -1.f;
        __syncthreads();
        unsigned u = 0; int mi = 0x7fffffff;
        for (int p = tid; p < NPTS; p += FPS_T)
            if (M[p]) { if (p < mi) { u = 1u; mi = p; } }
        int best = block_argmax(u, mi, &sh, lane, w, 0);
        int par = 1;
        for (int s = 0; s < NS; s++) {
            if (tid == 0) inds[s] = best;
            float lx = X[best * 3 + 0], ly = X[best * 3 + 1], lz = X[best * 3 + 2];
            unsigned mu = 0u; int mmi = 0x7fffffff;
            for (int p = tid; p < NPTS; p += FPS_T) {
                float dv = dist[p];
                if (dv >= 0.f) {
                    float dx = X[p * 3 + 0] - lx;
                    float dy = X[p * 3 + 1] - ly;
                    float dz = X[p * 3 + 2] - lz;
                    float d  = fmaf(dz, dz, fmaf(dy, dy, dx * dx));
                    dv = fminf(dv, d);
                    dist[p] = dv;
                    unsigned ub = __float_as_uint(dv);
                    if (ub > mu) { mu = ub; mmi = p; }
                }
            }
            best = block_argmax(mu, mmi, &sh, lane, w, par & 1);
            par ^= 1;
        }
    }
}

// ---------------------------------------------------------------- gathers
__global__ void gather_small(const float* __restrict__ xyz, float* __restrict__ out)
{
    int idx = blockIdx.x * blockDim.x + threadIdx.x;
    if (idx >= BB * NS) return;
    int b = idx >> 10;
    int ind = g_inds[idx];
    const float* p = xyz + ((long)b * NPTS + ind) * 3;
    out[O_GXYZ + (long)idx * 3 + 0] = p[0];
    out[O_GXYZ + (long)idx * 3 + 1] = p[1];
    out[O_GXYZ + (long)idx * 3 + 2] = p[2];
    out[O_GIND + idx] = (float)ind;
    out[O_FP2 + idx]  = out[O_GRASP + (long)b * NPTS + ind];
}

__global__ void gather_feat(const float* __restrict__ feat, float* __restrict__ out)
{
    long gid = (long)blockIdx.x * blockDim.x + threadIdx.x;
    if (gid >= (long)BB * CCH * NS) return;
    int s = (int)(gid & (NS - 1));
    int c = (int)((gid >> 10) & 255);
    int b = (int)(gid >> 18);
    int ind = g_inds[b * NS + s];
    out[O_GFEAT + gid] = feat[((long)b * CCH + c) * NPTS + ind];
}

// ---------------------------------------------------------------- final: vp_xyz, top view, rot
__global__ void final_kernel(const float* __restrict__ c2w, const float* __restrict__ c2b,
                             float* __restrict__ out)
{
    __shared__ float sw[3 * CCH];
    __shared__ float svx[NV], svy[NV], svz[NV], svn[NV];
    int tid = threadIdx.x;
    for (int i = tid; i < 3 * CCH; i += blockDim.x) sw[i] = c2w[i];
    for (int i = tid; i < NV; i += blockDim.x) {
        svx[i] = g_views[i * 3 + 0];
        svy[i] = g_views[i * 3 + 1];
        svz[i] = g_views[i * 3 + 2];
        svn[i] = g_vnorm[i];
    }
    __syncthreads();
    int idx = blockIdx.x * blockDim.x + tid;
    if (idx >= BB * NS) return;
    int b = idx >> 10, s = idx & (NS - 1);
    const float* F = g_f + (long)b * CCH * NS + s;
    float v0 = c2b[0], v1 = c2b[1], v2 = c2b[2];
#pragma unroll 8
    for (int c = 0; c < CCH; c++) {
        float f = F[(long)c * NS];
        v0 += sw[c] * f;
        v1 += sw[CCH + c] * f;
        v2 += sw[2 * CCH + c] * f;
    }
    out[O_VPXYZ + (long)idx * 3 + 0] = v0;
    out[O_VPXYZ + (long)idx * 3 + 1] = v1;
    out[O_VPXYZ + (long)idx * 3 + 2] = v2;

    float pn = sqrtf(v0 * v0 + v1 * v1 + v2 * v2);
    float bs = -3.4e38f; int bi = 0;
    for (int v = 0; v < NV; v++) {
        float dot = svx[v] * v0 + svy[v] * v1 + svz[v] * v2;
        float den = fmaxf(svn[v] * pn, 1e-8f);
        float scv = dot / den;
        if (scv > bs) { bs = scv; bi = v; }
    }
    out[O_TOPV + idx] = (float)bi;

    float tx = -v0, ty = -v1, tz = -v2;
    float ayx = -ty, ayy = tx, ayz = 0.f;
    float ny = sqrtf(ayx * ayx + ayy * ayy + ayz * ayz);
    if (ny == 0.f) { ayx = 0.f; ayy = 1.f; ayz = 0.f; }
    float nx = sqrtf(tx * tx + ty * ty + tz * tz);
    float ax0 = tx / nx, ax1 = ty / nx, ax2 = tz / nx;
    float ny2 = sqrtf(ayx * ayx + ayy * ayy + ayz * ayz);
    float ay0 = ayx / ny2, ay1 = ayy / ny2, ay2 = ayz / ny2;
    float az0 = ax1 * ay2 - ax2 * ay1;
    float az1 = ax2 * ay0 - ax0 * ay2;
    float az2 = ax0 * ay1 - ax1 * ay0;
    float* R = out + O_VPROT + (long)idx * 9;
    R[0] = ax0; R[1] = ay0; R[2] = az0;
    R[3] = ax1; R[4] = ay1; R[5] = az1;
    R[6] = ax2; R[7] = ay2; R[8] = az2;
}

// ---------------------------------------------------------------- launch
extern "C" void kernel_launch(void* const* d_in, const int* in_sizes, int n_in,
                              void* d_out, int out_size)
{
    const float* seed_xyz  = (const float*)d_in[0];
    const float* seed_feat = (const float*)d_in[1];
    const float* gh_w1     = (const float*)d_in[2];
    const float* gh_b1     = (const float*)d_in[3];
    const float* gh_bn_g   = (const float*)d_in[4];
    const float* gh_bn_b   = (const float*)d_in[5];
    const float* gh_bn_m   = (const float*)d_in[6];
    const float* gh_bn_v   = (const float*)d_in[7];
    const float* gh_w2     = (const float*)d_in[8];
    const float* gh_b2     = (const float*)d_in[9];
    const float* c1_w      = (const float*)d_in[10];
    const float* c1_b      = (const float*)d_in[11];
    const float* bn1_g     = (const float*)d_in[12];
    const float* bn1_b     = (const float*)d_in[13];
    const float* bn1_m     = (const float*)d_in[14];
    const float* bn1_v     = (const float*)d_in[15];
    const float* c2_w      = (const float*)d_in[16];
    const float* c2_b      = (const float*)d_in[17];
    float* out = (float*)d_out;

    cudaFuncSetAttribute(fps_kernel, cudaFuncAttributeMaxDynamicSharedMemorySize, FPS_SMEM);

    float* fptr = 0;
    cudaGetSymbolAddress((void**)&fptr, g_f);

    views_kernel<<<1, 320>>>();

    // GEMM1 with fused graspable partial epilogue (h never materialized)
    gemm1_fused<<<dim3((NPTS + 127) / 128, 2, BB), 256>>>(
        gh_w1, seed_feat, gh_b1, gh_bn_g, gh_bn_b, gh_bn_m, gh_bn_v, gh_w2);

    graspable_combine<<<dim3((NPTS + 255) / 256, 1, BB), 256>>>(gh_b2, out);

    fps_kernel<<<BB, FPS_T, FPS_SMEM>>>(seed_xyz);

    gather_small<<<(BB * NS + 255) / 256, 256>>>(seed_xyz, out);
    gather_feat<<<(BB * CCH * NS + 255) / 256, 256>>>(seed_feat, out);

    sgemm_bn_relu<<<dim3(NS / 128, 2, BB), 256>>>(
        c1_w, out + O_GFEAT, (long)CCH * NS, fptr, (long)CCH * NS, NS,
        c1_b, bn1_g, bn1_b, bn1_m, bn1_v);

    final_kernel<<<(BB * NS + 255) / 256, 256>>>(c2_w, c2_b, out);
}

// round 9
// speedup vs baseline: 1.2149x; 1.0015x over previous
#include <cuda_runtime.h>
#include <math.h>

#define BB   4
#define NPTS 20000
#define CCH  256
#define NS   1024
#define NV   300

// output packing offsets (float32 elements, tuple order)
#define O_OBJ   0L
#define O_GRASP 160000L
#define O_GXYZ  240000L
#define O_GIND  252288L
#define O_GFEAT 256384L
#define O_FP2   1304960L
#define O_VPXYZ 1309056L
#define O_TOPV  1321344L
#define O_VPROT 1325440L

__device__ float g_part[BB * 2 * 3 * NPTS];
__device__ float g_f[BB * CCH * NS];
__device__ unsigned char g_mask[BB * NPTS];
__device__ int   g_inds[BB * NS];
__device__ float g_views[NV * 3];
__device__ float g_vnorm[NV];

// ---------------------------------------------------------------- packed f32x2 helpers
__device__ __forceinline__ unsigned long long pack2(float lo, float hi)
{
    unsigned long long r;
    asm("mov.b64 %0, {%1, %2};" : "=l"(r) : "f"(lo), "f"(hi));
    return r;
}
__device__ __forceinline__ void unpack2(unsigned long long v, float& lo, float& hi)
{
    asm("mov.b64 {%0, %1}, %2;" : "=f"(lo), "=f"(hi) : "l"(v));
}
__device__ __forceinline__ void ffma2(unsigned long long& d, unsigned long long a, unsigned long long b)
{
    asm("fma.rn.f32x2 %0, %1, %2, %0;" : "+l"(d) : "l"(a), "l"(b));
}
__device__ __forceinline__ unsigned long long add2(unsigned long long a, unsigned long long b)
{
    unsigned long long r;
    asm("add.rn.f32x2 %0, %1, %2;" : "=l"(r) : "l"(a), "l"(b));
    return r;
}
__device__ __forceinline__ unsigned long long mul2(unsigned long long a, unsigned long long b)
{
    unsigned long long r;
    asm("mul.rn.f32x2 %0, %1, %2;" : "=l"(r) : "l"(a), "l"(b));
    return r;
}
__device__ __forceinline__ unsigned long long fma2v(unsigned long long a, unsigned long long b,
                                                    unsigned long long c)
{
    unsigned long long r;
    asm("fma.rn.f32x2 %0, %1, %2, %3;" : "=l"(r) : "l"(a), "l"(b), "l"(c));
    return r;
}

// ---------------------------------------------------------------- views
__global__ void views_kernel()
{
    int i = blockIdx.x * blockDim.x + threadIdx.x;
    if (i >= NV) return;
    double phi = (sqrt(5.0) - 1.0) / 2.0;
    double z   = (2.0 * (double)i + 1.0) / (double)NV - 1.0;
    double r2  = 1.0 - z * z;
    double r   = sqrt(r2 > 0.0 ? r2 : 0.0);
    double ang = ((2.0 * 3.14159265358979323846) * (double)i) * phi;
    float x  = (float)(r * cos(ang));
    float y  = (float)(r * sin(ang));
    float zf = (float)z;
    g_views[i * 3 + 0] = x;
    g_views[i * 3 + 1] = y;
    g_views[i * 3 + 2] = zf;
    g_vnorm[i] = sqrtf(x * x + y * y + zf * zf);
}

// ---------------------------------------------------------------- GEMM1 (R4 mainloop) + fused graspable partial epilogue
__global__ __launch_bounds__(256, 2) void gemm1_fused(
                              const float* __restrict__ W,
                              const float* __restrict__ Feat,
                              const float* __restrict__ bias,
                              const float* __restrict__ bng, const float* __restrict__ bnb,
                              const float* __restrict__ bnm, const float* __restrict__ bnv,
                              const float* __restrict__ w2)
{
    __shared__ __align__(16) float As[8][132];
    __shared__ __align__(16) float Bs[8][128];
    __shared__ float sw[3 * CCH];
    __shared__ float pr[16][3][128];
    const int b    = blockIdx.z;
    const int half = blockIdx.y;
    const int row0 = half * 128;
    const int col0 = blockIdx.x * 128;
    const float* Bb = Feat + (long)b * CCH * NPTS;
    const int tid  = threadIdx.x;
    const int trow = tid >> 4;
    const int tcol = tid & 15;
    const int ncols = NPTS;

    for (int i = tid; i < 3 * CCH; i += 256) sw[i] = w2[i];

    const int a_r  = tid >> 1;
    const int a_kg = (tid & 1) * 4;
    const int b_c  = (tid & 31) * 4;
    const int b_k  = tid >> 5;
    const int b_col = col0 + b_c;

    unsigned long long acc[8][4];
#pragma unroll
    for (int i = 0; i < 8; i++)
#pragma unroll
        for (int j = 0; j < 4; j++) acc[i][j] = 0ULL;

    float4 aReg, bReg;
    aReg = *reinterpret_cast<const float4*>(&W[(row0 + a_r) * CCH + a_kg]);
    if (b_col + 3 < ncols) {
        bReg = *reinterpret_cast<const float4*>(&Bb[(long)b_k * ncols + b_col]);
    } else {
        bReg.x = (b_col + 0 < ncols) ? Bb[(long)b_k * ncols + b_col + 0] : 0.f;
        bReg.y = (b_col + 1 < ncols) ? Bb[(long)b_k * ncols + b_col + 1] : 0.f;
        bReg.z = (b_col + 2 < ncols) ? Bb[(long)b_k * ncols + b_col + 2] : 0.f;
        bReg.w = (b_col + 3 < ncols) ? Bb[(long)b_k * ncols + b_col + 3] : 0.f;
    }

    for (int kc = 0; kc < CCH; kc += 8) {
        if (kc) __syncthreads();
        As[a_kg + 0][a_r] = aReg.x;
        As[a_kg + 1][a_r] = aReg.y;
        As[a_kg + 2][a_r] = aReg.z;
        As[a_kg + 3][a_r] = aReg.w;
        *reinterpret_cast<float4*>(&Bs[b_k][b_c]) = bReg;
        __syncthreads();

        if (kc + 8 < CCH) {
            aReg = *reinterpret_cast<const float4*>(&W[(row0 + a_r) * CCH + kc + 8 + a_kg]);
            if (b_col + 3 < ncols) {
                bReg = *reinterpret_cast<const float4*>(&Bb[(long)(kc + 8 + b_k) * ncols + b_col]);
            } else {
                bReg.x = (b_col + 0 < ncols) ? Bb[(long)(kc + 8 + b_k) * ncols + b_col + 0] : 0.f;
                bReg.y = (b_col + 1 < ncols) ? Bb[(long)(kc + 8 + b_k) * ncols + b_col + 1] : 0.f;
                bReg.z = (b_col + 2 < ncols) ? Bb[(long)(kc + 8 + b_k) * ncols + b_col + 2] : 0.f;
                bReg.w = (b_col + 3 < ncols) ? Bb[(long)(kc + 8 + b_k) * ncols + b_col + 3] : 0.f;
            }
        }

#pragma unroll
        for (int k = 0; k < 8; k++) {
            float4 a0 = *reinterpret_cast<const float4*>(&As[k][trow * 8]);
            float4 a1 = *reinterpret_cast<const float4*>(&As[k][trow * 8 + 4]);
            float4 b0 = *reinterpret_cast<const float4*>(&Bs[k][tcol * 4]);
            float4 b1 = *reinterpret_cast<const float4*>(&Bs[k][tcol * 4 + 64]);
            unsigned long long bb[4];
            bb[0] = pack2(b0.x, b0.y);
            bb[1] = pack2(b0.z, b0.w);
            bb[2] = pack2(b1.x, b1.y);
            bb[3] = pack2(b1.z, b1.w);
            float av[8] = {a0.x, a0.y, a0.z, a0.w, a1.x, a1.y, a1.z, a1.w};
#pragma unroll
            for (int i = 0; i < 8; i++) {
                unsigned long long aa = pack2(av[i], av[i]);
#pragma unroll
                for (int j = 0; j < 4; j++)
                    ffma2(acc[i][j], aa, bb[j]);
            }
        }
    }

    float p0[8], p1[8], p2[8];
#pragma unroll
    for (int j = 0; j < 8; j++) { p0[j] = 0.f; p1[j] = 0.f; p2[j] = 0.f; }
#pragma unroll
    for (int i = 0; i < 8; i++) {
        int row = row0 + trow * 8 + i;
        float sc = bng[row] / sqrtf(bnv[row] + 1e-5f);
        float sh = (bias[row] - bnm[row]) * sc + bnb[row];
        float w0 = sw[row], w1 = sw[CCH + row], wv = sw[2 * CCH + row];
        float v[8];
#pragma unroll
        for (int j = 0; j < 4; j++) unpack2(acc[i][j], v[2 * j], v[2 * j + 1]);
#pragma unroll
        for (int j = 0; j < 8; j++) {
            float h = fmaxf(v[j] * sc + sh, 0.f);
            p0[j] = fmaf(w0, h, p0[j]);
            p1[j] = fmaf(w1, h, p1[j]);
            p2[j] = fmaf(wv, h, p2[j]);
        }
    }
    __syncthreads();
#pragma unroll
    for (int g = 0; g < 2; g++) {
#pragma unroll
        for (int j = 0; j < 4; j++) {
            int c = tcol * 4 + g * 64 + j;
            pr[trow][0][c] = p0[4 * g + j];
            pr[trow][1][c] = p1[4 * g + j];
            pr[trow][2][c] = p2[4 * g + j];
        }
    }
    __syncthreads();
    for (int t = tid; t < 384; t += 256) {
        int ch = t >> 7, c = t & 127;
        float s = 0.f;
#pragma unroll
        for (int g = 0; g < 16; g++) s += pr[g][ch][c];
        int gcol = col0 + c;
        if (gcol < NPTS)
            g_part[(((long)b * 2 + half) * 3 + ch) * NPTS + gcol] = s;
    }
}

// ---------------------------------------------------------------- combine halves -> obj/grasp/mask
__global__ void graspable_combine(const float* __restrict__ b2, float* __restrict__ out)
{
    int b = blockIdx.z;
    int n = blockIdx.x * blockDim.x + threadIdx.x;
    if (n >= NPTS) return;
    const float* P0 = g_part + ((long)b * 2 + 0) * 3 * NPTS;
    const float* P1 = g_part + ((long)b * 2 + 1) * 3 * NPTS;
    float s0 = b2[0] + P0[0 * NPTS + n] + P1[0 * NPTS + n];
    float s1 = b2[1] + P0[1 * NPTS + n] + P1[1 * NPTS + n];
    float s2 = b2[2] + P0[2 * NPTS + n] + P1[2 * NPTS + n];
    out[O_OBJ + ((long)b * 2) * NPTS + n]     = s0;
    out[O_OBJ + ((long)b * 2 + 1) * NPTS + n] = s1;
    out[O_GRASP + (long)b * NPTS + n]         = s2;
    g_mask[b * NPTS + n] = (unsigned char)((s1 > s0) && (s2 > 0.1f));
}

// ---------------------------------------------------------------- GEMM2 (R4-proven 128x128)
__global__ __launch_bounds__(256, 2) void sgemm_bn_relu(
                              const float* __restrict__ W,
                              const float* __restrict__ Bmat, long strideB,
                              float* __restrict__ Cmat, long strideC,
                              int ncols,
                              const float* __restrict__ bias,
                              const float* __restrict__ bng, const float* __restrict__ bnb,
                              const float* __restrict__ bnm, const float* __restrict__ bnv)
{
    __shared__ __align__(16) float As[8][132];
    __shared__ __align__(16) float Bs[8][128];
    const int b    = blockIdx.z;
    const int row0 = blockIdx.y * 128;
    const int col0 = blockIdx.x * 128;
    const float* Bb = Bmat + (long)b * strideB;
    float* Cb = Cmat + (long)b * strideC;
    const int tid  = threadIdx.x;
    const int trow = tid >> 4;
    const int tcol = tid & 15;

    const int a_r  = tid >> 1;
    const int a_kg = (tid & 1) * 4;
    const int b_c  = (tid & 31) * 4;
    const int b_k  = tid >> 5;
    const int b_col = col0 + b_c;

    unsigned long long acc[8][4];
#pragma unroll
    for (int i = 0; i < 8; i++)
#pragma unroll
        for (int j = 0; j < 4; j++) acc[i][j] = 0ULL;

    float4 aReg, bReg;
    aReg = *reinterpret_cast<const float4*>(&W[(row0 + a_r) * CCH + a_kg]);
    if (b_col + 3 < ncols) {
        bReg = *reinterpret_cast<const float4*>(&Bb[(long)b_k * ncols + b_col]);
    } else {
        bReg.x = (b_col + 0 < ncols) ? Bb[(long)b_k * ncols + b_col + 0] : 0.f;
        bReg.y = (b_col + 1 < ncols) ? Bb[(long)b_k * ncols + b_col + 1] : 0.f;
        bReg.z = (b_col + 2 < ncols) ? Bb[(long)b_k * ncols + b_col + 2] : 0.f;
        bReg.w = (b_col + 3 < ncols) ? Bb[(long)b_k * ncols + b_col + 3] : 0.f;
    }

    for (int kc = 0; kc < CCH; kc += 8) {
        if (kc) __syncthreads();
        As[a_kg + 0][a_r] = aReg.x;
        As[a_kg + 1][a_r] = aReg.y;
        As[a_kg + 2][a_r] = aReg.z;
        As[a_kg + 3][a_r] = aReg.w;
        *reinterpret_cast<float4*>(&Bs[b_k][b_c]) = bReg;
        __syncthreads();

        if (kc + 8 < CCH) {
            aReg = *reinterpret_cast<const float4*>(&W[(row0 + a_r) * CCH + kc + 8 + a_kg]);
            if (b_col + 3 < ncols) {
                bReg = *reinterpret_cast<const float4*>(&Bb[(long)(kc + 8 + b_k) * ncols + b_col]);
            } else {
                bReg.x = (b_col + 0 < ncols) ? Bb[(long)(kc + 8 + b_k) * ncols + b_col + 0] : 0.f;
                bReg.y = (b_col + 1 < ncols) ? Bb[(long)(kc + 8 + b_k) * ncols + b_col + 1] : 0.f;
                bReg.z = (b_col + 2 < ncols) ? Bb[(long)(kc + 8 + b_k) * ncols + b_col + 2] : 0.f;
                bReg.w = (b_col + 3 < ncols) ? Bb[(long)(kc + 8 + b_k) * ncols + b_col + 3] : 0.f;
            }
        }

#pragma unroll
        for (int k = 0; k < 8; k++) {
            float4 a0 = *reinterpret_cast<const float4*>(&As[k][trow * 8]);
            float4 a1 = *reinterpret_cast<const float4*>(&As[k][trow * 8 + 4]);
            float4 b0 = *reinterpret_cast<const float4*>(&Bs[k][tcol * 4]);
            float4 b1 = *reinterpret_cast<const float4*>(&Bs[k][tcol * 4 + 64]);
            unsigned long long bb[4];
            bb[0] = pack2(b0.x, b0.y);
            bb[1] = pack2(b0.z, b0.w);
            bb[2] = pack2(b1.x, b1.y);
            bb[3] = pack2(b1.z, b1.w);
            float av[8] = {a0.x, a0.y, a0.z, a0.w, a1.x, a1.y, a1.z, a1.w};
#pragma unroll
            for (int i = 0; i < 8; i++) {
                unsigned long long aa = pack2(av[i], av[i]);
#pragma unroll
                for (int j = 0; j < 4; j++)
                    ffma2(acc[i][j], aa, bb[j]);
            }
        }
    }

#pragma unroll
    for (int i = 0; i < 8; i++) {
        int row = row0 + trow * 8 + i;
        float sc = bng[row] / sqrtf(bnv[row] + 1e-5f);
        float sh = (bias[row] - bnm[row]) * sc + bnb[row];
        float v[8];
#pragma unroll
        for (int j = 0; j < 4; j++) unpack2(acc[i][j], v[2 * j], v[2 * j + 1]);
#pragma unroll
        for (int g = 0; g < 2; g++) {
            int col = col0 + tcol * 4 + g * 64;
            float4 o;
            o.x = fmaxf(v[4 * g + 0] * sc + sh, 0.f);
            o.y = fmaxf(v[4 * g + 1] * sc + sh, 0.f);
            o.z = fmaxf(v[4 * g + 2] * sc + sh, 0.f);
            o.w = fmaxf(v[4 * g + 3] * sc + sh, 0.f);
            if (col + 3 < ncols) {
                *reinterpret_cast<float4*>(&Cb[(long)row * ncols + col]) = o;
            } else {
                if (col + 0 < ncols) Cb[(long)row * ncols + col + 0] = o.x;
                if (col + 1 < ncols) Cb[(long)row * ncols + col + 1] = o.y;
                if (col + 2 < ncols) Cb[(long)row * ncols + col + 2] = o.z;
                if (col + 3 < ncols) Cb[(long)row * ncols + col + 3] = o.w;
            }
        }
    }
}

// ---------------------------------------------------------------- FPS: hybrid packed math + R4 scalar bookkeeping
#define FPS_T    256
#define FPS_NW   8
#define FPS_CAP  13312
#define FPS_RNG  79
#define FPS_SMEM (FPS_CAP * 16)

__device__ __forceinline__ void argmax_redux(unsigned& u, int& mi)
{
    unsigned um;
    asm("redux.sync.max.u32 %0, %1, 0xffffffff;" : "=r"(um) : "r"(u));
    unsigned cand = (u == um) ? (unsigned)mi : 0x7fffffffu;
    unsigned bm;
    asm("redux.sync.min.u32 %0, %1, 0xffffffff;" : "=r"(bm) : "r"(cand));
    u = um; mi = (int)bm;
}

struct FpsShared {
    unsigned r_v[2][FPS_NW];
    int      r_i[2][FPS_NW];
};

__device__ __forceinline__ int block_argmax(unsigned u, int mi, FpsShared* sh,
                                            int lane, int w, int par)
{
    argmax_redux(u, mi);
    if (lane == 0) { sh->r_v[par][w] = u; sh->r_i[par][w] = mi; }
    __syncthreads();
    unsigned u2 = (lane < FPS_NW) ? sh->r_v[par][lane] : 0u;
    int mi2 = (lane < FPS_NW) ? sh->r_i[par][lane] : 0x7fffffff;
    argmax_redux(u2, mi2);
    return mi2;
}

// Hybrid reg variant: thread owns compact pairs {2t, 2t+1} + jp*2*FPS_T.
// Packed f32x2 distance math (per-lane bit-identical to scalar FADD/FFMA),
// then scalar R4 bookkeeping (fmin + strict-> keeps first on tie; ascending
// in-thread order + min-index redux == R4 tie semantics).
template<int PPT>
__device__ void fps_reg_loop(const float* s_x, const float* s_y, const float* s_z,
                             const int* s_i, int total, int* inds,
                             FpsShared* sh, int tid, int lane, int w)
{
    constexpr int NP2 = PPT / 2;
    unsigned long long pxp[NP2], pyp[NP2], pzp[NP2];
    float dist[PPT];
#pragma unroll
    for (int jp = 0; jp < NP2; jp++) {
        int c0 = 2 * tid + jp * 2 * FPS_T;
        bool ok0 = c0 < total, ok1 = c0 + 1 < total;
        pxp[jp] = pack2(ok0 ? s_x[c0] : 0.f, ok1 ? s_x[c0 + 1] : 0.f);
        pyp[jp] = pack2(ok0 ? s_y[c0] : 0.f, ok1 ? s_y[c0 + 1] : 0.f);
        pzp[jp] = pack2(ok0 ? s_z[c0] : 0.f, ok1 ? s_z[c0 + 1] : 0.f);
        dist[2 * jp + 0] = ok0 ? 1e10f : -1.f;
        dist[2 * jp + 1] = ok1 ? 1e10f : -1.f;
    }

    int best = 0;
    int par = 0;
    for (int s = 0; s < NS; s++) {
        if (tid == 0) inds[s] = s_i[best];
        float lx = s_x[best], ly = s_y[best], lz = s_z[best];
        unsigned long long nlx = pack2(-lx, -lx);
        unsigned long long nly = pack2(-ly, -ly);
        unsigned long long nlz = pack2(-lz, -lz);
        float mv = -0.5f; int mi = 0x7fffffff;
#pragma unroll
        for (int jp = 0; jp < NP2; jp++) {
            int c0 = 2 * tid + jp * 2 * FPS_T;
            unsigned long long dX = add2(pxp[jp], nlx);
            unsigned long long dY = add2(pyp[jp], nly);
            unsigned long long dZ = add2(pzp[jp], nlz);
            unsigned long long t  = mul2(dX, dX);
            t = fma2v(dY, dY, t);
            t = fma2v(dZ, dZ, t);
            float d0, d1;
            unpack2(t, d0, d1);
            float n0 = fminf(dist[2 * jp + 0], d0);
            dist[2 * jp + 0] = n0;
            if (n0 > mv) { mv = n0; mi = c0; }
            float n1 = fminf(dist[2 * jp + 1], d1);
            dist[2 * jp + 1] = n1;
            if (n1 > mv) { mv = n1; mi = c0 + 1; }
        }
        unsigned u = (mi == 0x7fffffff) ? 0u : __float_as_uint(mv);
        best = block_argmax(u, mi, sh, lane, w, par);
        par ^= 1;
    }
}

// Hybrid smem variant: LDS.64 pair loads + packed math, scalar bookkeeping.
template<int PPT>
__device__ void fps_smem_loop(const float* s_x, const float* s_y, const float* s_z,
                              const int* s_i, int total, int* inds,
                              FpsShared* sh, int tid, int lane, int w)
{
    constexpr int NP2 = PPT / 2;
    float dist[PPT];
#pragma unroll
    for (int jp = 0; jp < NP2; jp++) {
        int c0 = 2 * tid + jp * 2 * FPS_T;
        dist[2 * jp + 0] = (c0     < total) ? 1e10f : -1.f;
        dist[2 * jp + 1] = (c0 + 1 < total) ? 1e10f : -1.f;
    }

    int best = 0;
    int par = 0;
    for (int s = 0; s < NS; s++) {
        if (tid == 0) inds[s] = s_i[best];
        float lx = s_x[best], ly = s_y[best], lz = s_z[best];
        unsigned long long nlx = pack2(-lx, -lx);
        unsigned long long nly = pack2(-ly, -ly);
        unsigned long long nlz = pack2(-lz, -lz);
        float mv = -0.5f; int mi = 0x7fffffff;
#pragma unroll
        for (int jp = 0; jp < NP2; jp++) {
            int c0 = 2 * tid + jp * 2 * FPS_T;
            if (c0 + 1 < total) {
                unsigned long long px = *reinterpret_cast<const unsigned long long*>(&s_x[c0]);
                unsigned long long py = *reinterpret_cast<const unsigned long long*>(&s_y[c0]);
                unsigned long long pz = *reinterpret_cast<const unsigned long long*>(&s_z[c0]);
                unsigned long long dX = add2(px, nlx);
                unsigned long long dY = add2(py, nly);
                unsigned long long dZ = add2(pz, nlz);
                unsigned long long t  = mul2(dX, dX);
                t = fma2v(dY, dY, t);
                t = fma2v(dZ, dZ, t);
                float d0, d1;
                unpack2(t, d0, d1);
                float n0 = fminf(dist[2 * jp + 0], d0);
                dist[2 * jp + 0] = n0;
                if (n0 > mv) { mv = n0; mi = c0; }
                float n1 = fminf(dist[2 * jp + 1], d1);
                dist[2 * jp + 1] = n1;
                if (n1 > mv) { mv = n1; mi = c0 + 1; }
            } else if (c0 < total) {
                float dx = s_x[c0] - lx;
                float dy = s_y[c0] - ly;
                float dz = s_z[c0] - lz;
                float d  = fmaf(dz, dz, fmaf(dy, dy, dx * dx));
                float n0 = fminf(dist[2 * jp + 0], d);
                dist[2 * jp + 0] = n0;
                if (n0 > mv) { mv = n0; mi = c0; }
            }
        }
        unsigned u = (mi == 0x7fffffff) ? 0u : __float_as_uint(mv);
        best = block_argmax(u, mi, sh, lane, w, par);
        par ^= 1;
    }
}

__global__ __launch_bounds__(FPS_T, 1) void fps_kernel(const float* __restrict__ xyz)
{
    extern __shared__ unsigned char s_raw[];
    float* s_x = (float*)s_raw;
    float* s_y = s_x + FPS_CAP;
    float* s_z = s_y + FPS_CAP;
    int*   s_i = (int*)(s_z + FPS_CAP);

    __shared__ FpsShared sh;
    __shared__ int wsum[FPS_NW], woff[FPS_NW], s_total;

    const int b   = blockIdx.x;
    const int tid = threadIdx.x;
    const int lane = tid & 31, w = tid >> 5;
    const float* X = xyz + (long)b * NPTS * 3;
    const unsigned char* M = g_mask + b * NPTS;
    int* inds = g_inds + b * NS;

    int lo = tid * FPS_RNG;
    int hi = lo + FPS_RNG; if (hi > NPTS) hi = NPTS;
    if (lo > NPTS) lo = NPTS;
    int cnt = 0;
    for (int p = lo; p < hi; p++) cnt += M[p];

    int inc = cnt;
#pragma unroll
    for (int o = 1; o < 32; o <<= 1) {
        int v = __shfl_up_sync(0xffffffffu, inc, o);
        if (lane >= o) inc += v;
    }
    if (lane == 31) wsum[w] = inc;
    __syncthreads();
    if (tid < FPS_NW) {
        int v = wsum[tid];
        int iv = v;
#pragma unroll
        for (int o = 1; o < FPS_NW; o <<= 1) {
            int u = __shfl_up_sync(0x000000ffu, iv, o);
            if (tid >= o) iv += u;
        }
        woff[tid] = iv - v;
        if (tid == FPS_NW - 1) s_total = iv;
    }
    __syncthreads();
    const int total = s_total;
    int excl = woff[w] + (inc - cnt);

    if (total == 0) {
        for (int s = tid; s < NS; s += FPS_T) inds[s] = 0;
        return;
    }

    if (total <= FPS_CAP) {
        int pos = excl;
        for (int p = lo; p < hi; p++) {
            if (M[p]) {
                s_x[pos] = X[p * 3 + 0];
                s_y[pos] = X[p * 3 + 1];
                s_z[pos] = X[p * 3 + 2];
                s_i[pos] = p;
                pos++;
            }
        }
        __syncthreads();

        if      (total <= FPS_T * 6)  fps_reg_loop<6>  (s_x, s_y, s_z, s_i, total, inds, &sh, tid, lane, w);
        else if (total <= FPS_T * 12) fps_reg_loop<12> (s_x, s_y, s_z, s_i, total, inds, &sh, tid, lane, w);
        else if (total <= FPS_T * 18) fps_reg_loop<18> (s_x, s_y, s_z, s_i, total, inds, &sh, tid, lane, w);
        else if (total <= FPS_T * 24) fps_reg_loop<24> (s_x, s_y, s_z, s_i, total, inds, &sh, tid, lane, w);
        else if (total <= FPS_T * 36) fps_smem_loop<36>(s_x, s_y, s_z, s_i, total, inds, &sh, tid, lane, w);
        else                          fps_smem_loop<52>(s_x, s_y, s_z, s_i, total, inds, &sh, tid, lane, w);
    } else {
        float* dist = (float*)s_raw;
        for (int p = tid; p < NPTS; p += FPS_T)
            dist[p] = M[p] ? 1e10f : -1.f;
        __syncthreads();
        unsigned u = 0; int mi = 0x7fffffff;
        for (int p = tid; p < NPTS; p += FPS_T)
            if (M[p]) { if (p < mi) { u = 1u; mi = p; } }
        int best = block_argmax(u, mi, &sh, lane, w, 0);
        int par = 1;
        for (int s = 0; s < NS; s++) {
            if (tid == 0) inds[s] = best;
            float lx = X[best * 3 + 0], ly = X[best * 3 + 1], lz = X[best * 3 + 2];
            unsigned mu = 0u; int mmi = 0x7fffffff;
            for (int p = tid; p < NPTS; p += FPS_T) {
                float dv = dist[p];
                if (dv >= 0.f) {
                    float dx = X[p * 3 + 0] - lx;
                    float dy = X[p * 3 + 1] - ly;
                    float dz = X[p * 3 + 2] - lz;
                    float d  = fmaf(dz, dz, fmaf(dy, dy, dx * dx));
                    dv = fminf(dv, d);
                    dist[p] = dv;
                    unsigned ub = __float_as_uint(dv);
                    if (ub > mu) { mu = ub; mmi = p; }
                }
            }
            best = block_argmax(mu, mmi, &sh, lane, w, par & 1);
            par ^= 1;
        }
    }
}

// ---------------------------------------------------------------- merged gathers
__global__ void gathers_kernel(const float* __restrict__ xyz,
                               const float* __restrict__ feat,
                               float* __restrict__ out)
{
    long gid = (long)blockIdx.x * blockDim.x + threadIdx.x;
    if (gid < (long)BB * NS) {
        int idx = (int)gid;
        int b = idx >> 10;
        int ind = g_inds[idx];
        const float* p = xyz + ((long)b * NPTS + ind) * 3;
        out[O_GXYZ + (long)idx * 3 + 0] = p[0];
        out[O_GXYZ + (long)idx * 3 + 1] = p[1];
        out[O_GXYZ + (long)idx * 3 + 2] = p[2];
        out[O_GIND + idx] = (float)ind;
        out[O_FP2 + idx]  = out[O_GRASP + (long)b * NPTS + ind];
    }
    if (gid < (long)BB * CCH * NS) {
        int s = (int)(gid & (NS - 1));
        int c = (int)((gid >> 10) & 255);
        int b = (int)(gid >> 18);
        int ind = g_inds[b * NS + s];
        out[O_GFEAT + gid] = feat[((long)b * CCH + c) * NPTS + ind];
    }
}

// ---------------------------------------------------------------- final: vp_xyz, top view, rot
__global__ void final_kernel(const float* __restrict__ c2w, const float* __restrict__ c2b,
                             float* __restrict__ out)
{
    __shared__ float sw[3 * CCH];
    __shared__ float svx[NV], svy[NV], svz[NV], svn[NV];
    int tid = threadIdx.x;
    for (int i = tid; i < 3 * CCH; i += blockDim.x) sw[i] = c2w[i];
    for (int i = tid; i < NV; i += blockDim.x) {
        svx[i] = g_views[i * 3 + 0];
        svy[i] = g_views[i * 3 + 1];
        svz[i] = g_views[i * 3 + 2];
        svn[i] = g_vnorm[i];
    }
    __syncthreads();
    int idx = blockIdx.x * blockDim.x + tid;
    if (idx >= BB * NS) return;
    int b = idx >> 10, s = idx & (NS - 1);
    const float* F = g_f + (long)b * CCH * NS + s;
    float v0 = c2b[0], v1 = c2b[1], v2 = c2b[2];
#pragma unroll 8
    for (int c = 0; c < CCH; c++) {
        float f = F[(long)c * NS];
        v0 += sw[c] * f;
        v1 += sw[CCH + c] * f;
        v2 += sw[2 * CCH + c] * f;
    }
    out[O_VPXYZ + (long)idx * 3 + 0] = v0;
    out[O_VPXYZ + (long)idx * 3 + 1] = v1;
    out[O_VPXYZ + (long)idx * 3 + 2] = v2;

    float pn = sqrtf(v0 * v0 + v1 * v1 + v2 * v2);
    float bs = -3.4e38f; int bi = 0;
    for (int v = 0; v < NV; v++) {
        float dot = svx[v] * v0 + svy[v] * v1 + svz[v] * v2;
        float den = fmaxf(svn[v] * pn, 1e-8f);
        float scv = dot / den;
        if (scv > bs) { bs = scv; bi = v; }
    }
    out[O_TOPV + idx] = (float)bi;

    float tx = -v0, ty = -v1, tz = -v2;
    float ayx = -ty, ayy = tx, ayz = 0.f;
    float ny = sqrtf(ayx * ayx + ayy * ayy + ayz * ayz);
    if (ny == 0.f) { ayx = 0.f; ayy = 1.f; ayz = 0.f; }
    float nx = sqrtf(tx * tx + ty * ty + tz * tz);
    float ax0 = tx / nx, ax1 = ty / nx, ax2 = tz / nx;
    float ny2 = sqrtf(ayx * ayx + ayy * ayy + ayz * ayz);
    float ay0 = ayx / ny2, ay1 = ayy / ny2, ay2 = ayz / ny2;
    float az0 = ax1 * ay2 - ax2 * ay1;
    float az1 = ax2 * ay0 - ax0 * ay2;
    float az2 = ax0 * ay1 - ax1 * ay0;
    float* R = out + O_VPROT + (long)idx * 9;
    R[0] = ax0; R[1] = ay0; R[2] = az0;
    R[3] = ax1; R[4] = ay1; R[5] = az1;
    R[6] = ax2; R[7] = ay2; R[8] = az2;
}

// ---------------------------------------------------------------- launch
extern "C" void kernel_launch(void* const* d_in, const int* in_sizes, int n_in,
                              void* d_out, int out_size)
{
    const float* seed_xyz  = (const float*)d_in[0];
    const float* seed_feat = (const float*)d_in[1];
    const float* gh_w1     = (const float*)d_in[2];
    const float* gh_b1     = (const float*)d_in[3];
    const float* gh_bn_g   = (const float*)d_in[4];
    const float* gh_bn_b   = (const float*)d_in[5];
    const float* gh_bn_m   = (const float*)d_in[6];
    const float* gh_bn_v   = (const float*)d_in[7];
    const float* gh_w2     = (const float*)d_in[8];
    const float* gh_b2     = (const float*)d_in[9];
    const float* c1_w      = (const float*)d_in[10];
    const float* c1_b      = (const float*)d_in[11];
    const float* bn1_g     = (const float*)d_in[12];
    const float* bn1_b     = (const float*)d_in[13];
    const float* bn1_m     = (const float*)d_in[14];
    const float* bn1_v     = (const float*)d_in[15];
    const float* c2_w      = (const float*)d_in[16];
    const float* c2_b      = (const float*)d_in[17];
    float* out = (float*)d_out;

    cudaFuncSetAttribute(fps_kernel, cudaFuncAttributeMaxDynamicSharedMemorySize, FPS_SMEM);

    float* fptr = 0;
    cudaGetSymbolAddress((void**)&fptr, g_f);

    views_kernel<<<1, 320>>>();

    gemm1_fused<<<dim3((NPTS + 127) / 128, 2, BB), 256>>>(
        gh_w1, seed_feat, gh_b1, gh_bn_g, gh_bn_b, gh_bn_m, gh_bn_v, gh_w2);

    graspable_combine<<<dim3((NPTS + 255) / 256, 1, BB), 256>>>(gh_b2, out);

    fps_kernel<<<BB, FPS_T, FPS_SMEM>>>(seed_xyz);

    gathers_kernel<<<(BB * CCH * NS + 255) / 256, 256>>>(seed_xyz, seed_feat, out);

    sgemm_bn_relu<<<dim3(NS / 128, 2, BB), 256>>>(
        c1_w, out + O_GFEAT, (long)CCH * NS, fptr, (long)CCH * NS, NS,
        c1_b, bn1_g, bn1_b, bn1_m, bn1_v);

    final_kernel<<<(BB * NS + 255) / 256, 256>>>(c2_w, c2_b, out);
}